// round 14
// baseline (speedup 1.0000x reference)
#include <cuda_runtime.h>
#include <cstdint>

// ---------------- problem constants ----------------
#define DDIM    64
#define MTOT    1024
#define NTRAIN  4096
#define TM      128
#define TN      128
#define NSPLIT  (NTRAIN / TN)      // 32
#define MT      (MTOT / TM)        // 8
#define CC      901.6844f          // log2(e)/var, var = 0.0016
#define NKS     5                  // 4 data k-steps + 1 augmentation k-step
#define DTHR    (-0.166f)          // d <= -150/CC (=-0.16636) => exp2==0 exactly
#define SCW     64                 // scratch width: 32 splits * 2 n-warps

// Fragments in exact mma.m16n8k16 register layout, K padded to 80:
// A: [rb(64)][ks(5)][lane(32)] uint4 = (a0,a1,a2,a3)
// B: [nbp(256)][ks(5)][lane(32)] uint4 = (b0e,b1e,b0o,b1o)
__device__ uint4 g_afrag[64 * NKS * 32];
__device__ uint4 g_bfrag[256 * NKS * 32];
__device__ float g_scratch[MTOT * SCW];   // [m][split*2 + nw]
__device__ int   g_cnt[MT];

__device__ __forceinline__ uint32_t bf16x2_pack(float lo, float hi) {
    uint32_t r;
    asm("cvt.rn.bf16x2.f32 %0, %1, %2;" : "=r"(r) : "f"(hi), "f"(lo));
    return r;
}
__device__ __forceinline__ float ex2f(float x) {
    float y; asm("ex2.approx.f32 %0, %1;" : "=f"(y) : "f"(x)); return y;
}
__device__ __forceinline__ float bf16_rn(float x) {   // round to bf16, back to f32
    uint32_t u;
    asm("cvt.rn.bf16x2.f32 %0, %1, %1;" : "=r"(u) : "f"(x));
    u = (u & 0xFFFFu) << 16;
    return __uint_as_float(u);
}
__device__ __forceinline__ void mma16816(float d[4], const uint32_t a[4],
                                         uint32_t b0, uint32_t b1) {
    asm volatile("mma.sync.aligned.m16n8k16.row.col.f32.bf16.bf16.f32 "
                 "{%0,%1,%2,%3}, {%4,%5,%6,%7}, {%8,%9}, {%0,%1,%2,%3};"
                 : "+f"(d[0]), "+f"(d[1]), "+f"(d[2]), "+f"(d[3])
                 : "r"(a[0]), "r"(a[1]), "r"(a[2]), "r"(a[3]),
                   "r"(b0), "r"(b1));
}
__device__ __forceinline__ int atom_arrive(int* p) {
    int old;
    asm volatile("atom.add.acq_rel.gpu.s32 %0, [%1], 1;"
                 : "=r"(old) : "l"(p) : "memory");
    return old;
}

// ---- Kernel 1: fragment conversion + norm augmentation (8 threads/row) ----
__global__ __launch_bounds__(256)
void kde_prep(const float* __restrict__ test_x,
              const float* __restrict__ train_x)
{
    const int gid = blockIdx.x * 256 + threadIdx.x;   // 0..40959
    const int row = gid >> 3;
    const int j   = gid & 7;
    const bool isA = (row < MTOT);
    const int  r   = isA ? row : row - MTOT;
    const float4* src =
        (const float4*)((isA ? test_x : train_x) + (size_t)r * DDIM) + j * 2;

    float4 v0 = src[0], v1 = src[1];
    float s = v0.x*v0.x + v0.y*v0.y + v0.z*v0.z + v0.w*v0.w
            + v1.x*v1.x + v1.y*v1.y + v1.z*v1.z + v1.w*v1.w;
    s += __shfl_xor_sync(~0u, s, 1);
    s += __shfl_xor_sync(~0u, s, 2);
    s += __shfl_xor_sync(~0u, s, 4);

    uint32_t p[4] = { bf16x2_pack(v0.x, v0.y), bf16x2_pack(v0.z, v0.w),
                      bf16x2_pack(v1.x, v1.y), bf16x2_pack(v1.z, v1.w) };
    const int ks = j >> 1, jh = j & 1;
    const int laneb = (r & 7) * 4;

    // ---- data k-steps 0..3 (identical mapping to the proven R7 prep) ----
    if (isA) {
        int aidx = jh * 2 + ((r >> 3) & 1);
        uint32_t* dst = (uint32_t*)g_afrag +
            ((((r >> 4) * NKS + ks) * 32 + laneb) * 4 + aidx);
        #pragma unroll
        for (int t = 0; t < 4; t++) dst[t * 4] = p[t];
    } else {
        int comp = ((r >> 3) & 1) * 2 + jh;
        uint32_t* dst = (uint32_t*)g_bfrag +
            ((((r >> 4) * NKS + ks) * 32 + laneb) * 4 + comp);
        #pragma unroll
        for (int t = 0; t < 4; t++) dst[t * 4] = p[t];
    }

    // ---- augmentation k-step 4 (threads j==0 and j==4 write it) ----
    if ((j & 3) == 0) {
        const int top = j >> 2;                 // 0: k64-71 pairs, 1: k72-79
        const float hn  = 0.5f * s;             // 0.5*||x||^2 (exact fp32)
        const float hif = bf16_rn(hn);
        const float lof = hn - hif;             // hi/lo split, err ~2^-16 rel

        uint32_t vals[4] = {0u, 0u, 0u, 0u};
        if (isA) {
            if (top == 0) {
                vals[0] = bf16x2_pack(hif, lof);    // k64,65
                vals[1] = bf16x2_pack(1.0f, 1.0f);  // k66,67
            }
            int aidx = top * 2 + ((r >> 3) & 1);
            uint32_t* dst = (uint32_t*)g_afrag +
                ((((r >> 4) * NKS + 4) * 32 + laneb) * 4 + aidx);
            #pragma unroll
            for (int t = 0; t < 4; t++) dst[t * 4] = vals[t];
        } else {
            if (top == 0) {
                vals[0] = bf16x2_pack(-1.0f, -1.0f);  // k64,65
                vals[1] = bf16x2_pack(-hif, -lof);    // k66,67
            }
            int comp = ((r >> 3) & 1) * 2 + top;
            uint32_t* dst = (uint32_t*)g_bfrag +
                ((((r >> 4) * NKS + 4) * 32 + laneb) * 4 + comp);
            #pragma unroll
            for (int t = 0; t < 4; t++) dst[t * 4] = vals[t];
        }
    }
}

// ---- Kernel 2: norm-free fragment-direct GEMM + fused reduction ----
__global__ __launch_bounds__(256, 2)
void kde_mma(float* __restrict__ out)
{
    const int tid = threadIdx.x;
    const int wid = tid >> 5;
    const int lid = tid & 31;
    const int m0  = blockIdx.x * TM;
    const int n0  = blockIdx.y * TN;

    const int mw = wid & 3;        // warp rows: m0+mw*32 .. +31
    const int nw = wid >> 2;       // warp cols: n0+nw*64 .. +63
    const int g  = lid >> 2;
    const int tk = lid & 3;

    // A fragments: 10 coalesced LDG.128, resident all loop
    uint4 aF[2][NKS];
    {
        const int rbb = (m0 >> 4) + mw * 2;
        #pragma unroll
        for (int mt = 0; mt < 2; mt++)
            #pragma unroll
            for (int ks = 0; ks < NKS; ks++)
                aF[mt][ks] = g_afrag[(((rbb + mt) * NKS + ks) << 5) + lid];
    }

    float acc[2][2] = {{0.f, 0.f}, {0.f, 0.f}};
    const int nbpb = (n0 >> 4) + nw * 4;

    #pragma unroll
    for (int p = 0; p < 4; p++) {
        uint4 bF[NKS];
        #pragma unroll
        for (int ks = 0; ks < NKS; ks++)
            bF[ks] = g_bfrag[(((nbpb + p) * NKS + ks) << 5) + lid];

        float d[2][2][4];
        #pragma unroll
        for (int mt = 0; mt < 2; mt++)
            #pragma unroll
            for (int c = 0; c < 2; c++)
                #pragma unroll
                for (int q = 0; q < 4; q++) d[mt][c][q] = 0.f;

        #pragma unroll
        for (int ks = 0; ks < NKS; ks++)
            #pragma unroll
            for (int mt = 0; mt < 2; mt++) {
                mma16816(d[mt][0], (const uint32_t*)&aF[mt][ks], bF[ks].x, bF[ks].y);
                mma16816(d[mt][1], (const uint32_t*)&aF[mt][ks], bF[ks].z, bF[ks].w);
            }

        // d = a.b - 0.5||a||^2 - 0.5||b||^2 already; constant flush guard
        float m01 = fmaxf(fmaxf(d[0][0][0], d[0][0][1]), fmaxf(d[0][0][2], d[0][0][3]));
        float m23 = fmaxf(fmaxf(d[0][1][0], d[0][1][1]), fmaxf(d[0][1][2], d[0][1][3]));
        float m45 = fmaxf(fmaxf(d[1][0][0], d[1][0][1]), fmaxf(d[1][0][2], d[1][0][3]));
        float m67 = fmaxf(fmaxf(d[1][1][0], d[1][1][1]), fmaxf(d[1][1][2], d[1][1][3]));
        float mx  = fmaxf(fmaxf(m01, m23), fmaxf(m45, m67));

        if (mx > DTHR) {   // rare exact path: exp2(CC*d)
            #pragma unroll
            for (int mt = 0; mt < 2; mt++)
                #pragma unroll
                for (int c = 0; c < 2; c++) {
                    acc[mt][0] += ex2f(d[mt][c][0] * CC) + ex2f(d[mt][c][1] * CC);
                    acc[mt][1] += ex2f(d[mt][c][2] * CC) + ex2f(d[mt][c][3] * CC);
                }
        }
    }

    // ---- lane-reduce over tk; tk==0 lanes STG strip sums straight to scratch ----
    #pragma unroll
    for (int mt = 0; mt < 2; mt++)
        #pragma unroll
        for (int rr = 0; rr < 2; rr++) {
            float v = acc[mt][rr];
            v += __shfl_xor_sync(~0u, v, 1);
            v += __shfl_xor_sync(~0u, v, 2);
            acc[mt][rr] = v;
        }
    if (tk == 0) {
        const int col = blockIdx.y * 2 + nw;
        #pragma unroll
        for (int mt = 0; mt < 2; mt++) {
            int r0 = m0 + mw * 32 + mt * 16 + g;
            g_scratch[(size_t)r0 * SCW + col]       = acc[mt][0];
            g_scratch[(size_t)(r0 + 8) * SCW + col] = acc[mt][1];
        }
    }
    __syncthreads();   // order all warps' STGs before the release-arrive

    // ---- counter + winner tail, entirely in warp 0 ----
    if (wid == 0) {
        int old = 0;
        if (lid == 0) old = atom_arrive(&g_cnt[blockIdx.x]);
        old = __shfl_sync(~0u, old, 0);
        if (old == NSPLIT - 1) {                 // last CTA of this m-row
            if (lid == 0) g_cnt[blockIdx.x] = 0; // reset for graph replay
            #pragma unroll
            for (int rr = 0; rr < 4; rr++) {     // 4 rows per lane
                int m = m0 + lid * 4 + rr;
                const float4* pr = (const float4*)&g_scratch[(size_t)m * SCW];
                float s = 0.f;
                #pragma unroll
                for (int j = 0; j < SCW / 4; j++) {   // 16 LDG.128
                    float4 v = pr[j];
                    s += (v.x + v.y) + (v.z + v.w);
                }
                out[m] = s * (9.973557010f / 4096.0f);  // rsqrt(2*pi*var)/N
            }
        }
    }
}

extern "C" void kernel_launch(void* const* d_in, const int* in_sizes, int n_in,
                              void* d_out, int out_size)
{
    const float* test_x  = (const float*)d_in[0];   // [1024,64]
    const float* train_x = (const float*)d_in[1];   // [4096,64]
    float* out = (float*)d_out;                     // [1024]

    kde_prep<<<(MTOT + NTRAIN) * 8 / 256, 256>>>(test_x, train_x);
    dim3 grid(MT, NSPLIT);   // (8,32) = 256 CTAs
    kde_mma<<<grid, 256>>>(out);
}

// round 15
// speedup vs baseline: 1.2381x; 1.2381x over previous
#include <cuda_runtime.h>
#include <cstdint>

// ---------------- problem constants ----------------
#define DDIM    64
#define MTOT    1024
#define NTRAIN  4096
#define TM      128                // CTA M tile
#define TN      128                // CTA N tile
#define NSPLIT  (NTRAIN / TN)      // 32
#define MT      (MTOT / TM)        // 8
#define CC      901.6844f          // log2(e)/var, var = 0.0016
#define HS      450.8422f          // 0.5*CC
#define INVCC   (1.0f / 901.6844f)

// deterministic cross-block scratch + self-resetting counters
__device__ float g_scratch[NSPLIT * MTOT];
__device__ int   g_cnt[MT];

struct SmemT {
    alignas(1024) unsigned char A[TM * 128];   // bf16 [row][64], SW128 (raw)
    alignas(1024) unsigned char B[TN * 128];   // bf16 [row][64], SW128 (raw)
    float hsa[TM];     // HS * ||a||^2 (exact fp32)
    float hsb[TN];     // HS * ||b||^2
    float red[2][TM];
};

__device__ __forceinline__ uint32_t smem_u32(const void* p) {
    return (uint32_t)__cvta_generic_to_shared(p);
}
__device__ __forceinline__ uint32_t bf16x2_pack(float lo, float hi) {
    uint32_t r;
    asm("cvt.rn.bf16x2.f32 %0, %1, %2;" : "=r"(r) : "f"(hi), "f"(lo));
    return r;
}
__device__ __forceinline__ float ex2f(float x) {
    float y; asm("ex2.approx.f32 %0, %1;" : "=f"(y) : "f"(x)); return y;
}
__device__ __forceinline__ uint32_t sw128(uint32_t o) {
    return o ^ ((o >> 3) & 0x70);
}
__device__ __forceinline__ void ldsm4(uint32_t r[4], uint32_t addr) {
    asm volatile("ldmatrix.sync.aligned.m8n8.x4.shared.b16 {%0,%1,%2,%3}, [%4];"
                 : "=r"(r[0]), "=r"(r[1]), "=r"(r[2]), "=r"(r[3]) : "r"(addr));
}
__device__ __forceinline__ void mma16816(float d[4], const uint32_t a[4],
                                         uint32_t b0, uint32_t b1) {
    asm volatile("mma.sync.aligned.m16n8k16.row.col.f32.bf16.bf16.f32 "
                 "{%0,%1,%2,%3}, {%4,%5,%6,%7}, {%8,%9}, {%0,%1,%2,%3};"
                 : "+f"(d[0]), "+f"(d[1]), "+f"(d[2]), "+f"(d[3])
                 : "r"(a[0]), "r"(a[1]), "r"(a[2]), "r"(a[3]),
                   "r"(b0), "r"(b1));
}

__global__ __launch_bounds__(256, 2)
void kde_mma(const float* __restrict__ test_x,
             const float* __restrict__ train_x,
             float* __restrict__ out)
{
    __shared__ SmemT smem;
    __shared__ int is_last;

    const int tid = threadIdx.x;
    const int wid = tid >> 5;
    const int lid = tid & 31;
    const int m0  = blockIdx.x * TM;
    const int n0  = blockIdx.y * TN;

    // ---- Convert A tile: 8 threads/row, 2xLDG.128 + 3-shfl norm + STS.128 ----
    {
        const float4* ta = (const float4*)(test_x + (size_t)m0 * DDIM);
        #pragma unroll
        for (int i = 0; i < 4; i++) {             // A: 1024 8-float chunks
            int idx = i * 256 + tid;
            int r = idx >> 3, j = idx & 7;
            float4 v0 = ta[idx * 2], v1 = ta[idx * 2 + 1];
            float s = v0.x*v0.x + v0.y*v0.y + v0.z*v0.z + v0.w*v0.w
                    + v1.x*v1.x + v1.y*v1.y + v1.z*v1.z + v1.w*v1.w;
            s += __shfl_xor_sync(~0u, s, 1);
            s += __shfl_xor_sync(~0u, s, 2);
            s += __shfl_xor_sync(~0u, s, 4);
            if (j == 0) smem.hsa[r] = HS * s;
            uint4 pk = make_uint4(bf16x2_pack(v0.x, v0.y), bf16x2_pack(v0.z, v0.w),
                                  bf16x2_pack(v1.x, v1.y), bf16x2_pack(v1.z, v1.w));
            *(uint4*)(smem.A + sw128((uint32_t)(r * 128 + j * 16))) = pk;
        }
    }
    __syncthreads();   // A + hsa visible

    // ---- Warp tiling: warp (mw, nw) owns rows mw*32..+31, cols nw*64..+63 ----
    const int mw = wid & 3;
    const int nw = wid >> 2;
    const uint32_t baseA = smem_u32(smem.A);
    const uint32_t baseB = smem_u32(smem.B);

    // A fragments: issue ldsm now so latency overlaps B's global loads below
    uint32_t aF[2][4][4];
    {
        int arow = mw * 32 + (lid & 7) + ((lid >> 3) & 1) * 8;
        int acol = (lid >> 4) * 16;
        #pragma unroll
        for (int mt = 0; mt < 2; mt++)
            #pragma unroll
            for (int ks = 0; ks < 4; ks++)
                ldsm4(aF[mt][ks],
                      baseA + sw128((uint32_t)((arow + mt * 16) * 128 + ks * 32 + acol)));
    }
    const int g  = lid >> 2;    // row within 8-group (mma C layout)
    const int tk = lid & 3;     // col-pair
    float hra[2][2];
    #pragma unroll
    for (int mt = 0; mt < 2; mt++) {
        hra[mt][0] = smem.hsa[mw * 32 + mt * 16 + g];
        hra[mt][1] = smem.hsa[mw * 32 + mt * 16 + g + 8];
    }

    // ---- Convert B tile (same 8-thread/row scheme) ----
    {
        const float4* tb = (const float4*)(train_x + (size_t)n0 * DDIM);
        #pragma unroll
        for (int i = 0; i < 4; i++) {             // B: 1024 8-float chunks
            int idx = i * 256 + tid;
            int r = idx >> 3, j = idx & 7;
            float4 v0 = tb[idx * 2], v1 = tb[idx * 2 + 1];
            float s = v0.x*v0.x + v0.y*v0.y + v0.z*v0.z + v0.w*v0.w
                    + v1.x*v1.x + v1.y*v1.y + v1.z*v1.z + v1.w*v1.w;
            s += __shfl_xor_sync(~0u, s, 1);
            s += __shfl_xor_sync(~0u, s, 2);
            s += __shfl_xor_sync(~0u, s, 4);
            if (j == 0) smem.hsb[r] = HS * s;
            uint4 pk = make_uint4(bf16x2_pack(v0.x, v0.y), bf16x2_pack(v0.z, v0.w),
                                  bf16x2_pack(v1.x, v1.y), bf16x2_pack(v1.z, v1.w));
            *(uint4*)(smem.B + sw128((uint32_t)(r * 128 + j * 16))) = pk;
        }
    }
    __syncthreads();   // B + hsb visible

    // per-warp conservative flush threshold (exact: exp2(x)=0 in fp32, x<=-150)
    float thr;
    {
        float va = smem.hsa[mw * 32 + lid];
        float vb = fminf(smem.hsb[nw * 64 + lid], smem.hsb[nw * 64 + 32 + lid]);
        #pragma unroll
        for (int s = 16; s; s >>= 1) {
            va = fminf(va, __shfl_xor_sync(~0u, va, s));
            vb = fminf(vb, __shfl_xor_sync(~0u, vb, s));
        }
        thr = (va + vb - 151.0f) * INVCC;   // d <= thr  =>  all exp2 == 0
    }

    // B ldmatrix.x4 base addresses: lanes 0-15 -> chunk p*2, lanes 16-31 -> p*2+1
    uint32_t bAddr4[4];
    {
        int rowb = nw * 64 + ((lid >> 4) & 1) * 8 + (lid & 7);
        int colb = ((lid >> 3) & 1) * 16;
        #pragma unroll
        for (int ks = 0; ks < 4; ks++)
            bAddr4[ks] = baseB + sw128((uint32_t)(rowb * 128 + ks * 32 + colb));
    }

    float acc[2][2] = {{0.f, 0.f}, {0.f, 0.f}};

    #pragma unroll
    for (int p = 0; p < 4; p++) {                 // 4 pairs of 8-col chunks
        const uint32_t boff = (uint32_t)p * 2048; // +16 rows; swizzle-invariant
        uint32_t bF[4][4];
        #pragma unroll
        for (int ks = 0; ks < 4; ks++)
            ldsm4(bF[ks], bAddr4[ks] + boff);

        float d[2][2][4];                          // [mt][chunk-in-pair][4]
        #pragma unroll
        for (int mt = 0; mt < 2; mt++)
            #pragma unroll
            for (int c = 0; c < 2; c++)
                #pragma unroll
                for (int q = 0; q < 4; q++) d[mt][c][q] = 0.f;

        #pragma unroll
        for (int ks = 0; ks < 4; ks++)
            #pragma unroll
            for (int mt = 0; mt < 2; mt++) {
                mma16816(d[mt][0], aF[mt][ks], bF[ks][0], bF[ks][1]);
                mma16816(d[mt][1], aF[mt][ks], bF[ks][2], bF[ks][3]);
            }

        // pairwise max tree over the 16 raw dot values
        float m01 = fmaxf(fmaxf(d[0][0][0], d[0][0][1]), fmaxf(d[0][0][2], d[0][0][3]));
        float m23 = fmaxf(fmaxf(d[0][1][0], d[0][1][1]), fmaxf(d[0][1][2], d[0][1][3]));
        float m45 = fmaxf(fmaxf(d[1][0][0], d[1][0][1]), fmaxf(d[1][0][2], d[1][0][3]));
        float m67 = fmaxf(fmaxf(d[1][1][0], d[1][1][1]), fmaxf(d[1][1][2], d[1][1][3]));
        float mx  = fmaxf(fmaxf(m01, m23), fmaxf(m45, m67));

        if (mx > thr) {   // rare exact path
            float2 hb0 = *(const float2*)&smem.hsb[nw * 64 + p * 16 + tk * 2];
            float2 hb1 = *(const float2*)&smem.hsb[nw * 64 + p * 16 + 8 + tk * 2];
            #pragma unroll
            for (int mt = 0; mt < 2; mt++)
                #pragma unroll
                for (int c = 0; c < 2; c++) {
                    float hbx = c ? hb1.x : hb0.x;
                    float hby = c ? hb1.y : hb0.y;
                    acc[mt][0] += ex2f(fmaf(d[mt][c][0], CC, -(hra[mt][0] + hbx)))
                                + ex2f(fmaf(d[mt][c][1], CC, -(hra[mt][0] + hby)));
                    acc[mt][1] += ex2f(fmaf(d[mt][c][2], CC, -(hra[mt][1] + hbx)))
                                + ex2f(fmaf(d[mt][c][3], CC, -(hra[mt][1] + hby)));
                }
        }
    }

    // ---- reduce across the 4 col-pair lanes; write per-(nw) row sums ----
    #pragma unroll
    for (int mt = 0; mt < 2; mt++)
        #pragma unroll
        for (int rr = 0; rr < 2; rr++) {
            float v = acc[mt][rr];
            v += __shfl_xor_sync(~0u, v, 1);
            v += __shfl_xor_sync(~0u, v, 2);
            acc[mt][rr] = v;
        }
    if (tk == 0) {
        #pragma unroll
        for (int mt = 0; mt < 2; mt++) {
            smem.red[nw][mw * 32 + mt * 16 + g]     = acc[mt][0];
            smem.red[nw][mw * 32 + mt * 16 + g + 8] = acc[mt][1];
        }
    }
    __syncthreads();

    if (tid < TM)
        g_scratch[blockIdx.y * MTOT + m0 + tid] =
            smem.red[0][tid] + smem.red[1][tid];

    // ---- last block per m-tile: deterministic final reduction ----
    if (tid == 0) {
        __threadfence();
        int old = atomicAdd(&g_cnt[blockIdx.x], 1);
        is_last = (old == NSPLIT - 1);
        if (is_last) g_cnt[blockIdx.x] = 0;   // reset for graph replay
    }
    __syncthreads();
    if (is_last) {
        __threadfence();
        if (tid < TM) {
            float s = 0.f;
            #pragma unroll
            for (int j = 0; j < NSPLIT; j++)
                s += g_scratch[j * MTOT + m0 + tid];
            out[m0 + tid] = s * (9.973557010f / 4096.0f);  // rsqrt(2*pi*var)/N
        }
    }
}

extern "C" void kernel_launch(void* const* d_in, const int* in_sizes, int n_in,
                              void* d_out, int out_size)
{
    const float* test_x  = (const float*)d_in[0];   // [1024,64]
    const float* train_x = (const float*)d_in[1];   // [4096,64]
    float* out = (float*)d_out;                     // [1024]

    dim3 grid(MT, NSPLIT);   // (8,32) = 256 CTAs, one wave @ occ 2
    kde_mma<<<grid, 256>>>(test_x, train_x, out);
}